// round 10
// baseline (speedup 1.0000x reference)
#include <cuda_runtime.h>
#include <cstdint>

#define NT      9
#define SEQ     512
#define BATCH   64
#define EMB     1024
#define NQ      8               // sequence eighths (scan blocks per batch)
#define CHUNK_LEN 8
#define CPB     8               // chunks per block
#define EMP     12

#define L2E 1.4426950408889634f
#define LN2 0.6931471805599453f

__device__ float g_M[BATCH * NQ * 81];
__device__ int   g_tags64;

__device__ __forceinline__ void ffma2(unsigned long long& acc,
                                      unsigned long long a,
                                      unsigned long long b)
{
    asm("fma.rn.f32x2 %0, %1, %2, %3;" : "=l"(acc) : "l"(a), "l"(b), "l"(acc));
}
__device__ __forceinline__ unsigned long long dup2(float x)
{
    unsigned long long r; asm("mov.b64 %0, {%1,%1};" : "=l"(r) : "f"(x)); return r;
}
__device__ __forceinline__ float fast_ex2(float x)
{
    float r; asm("ex2.approx.ftz.f32 %0, %1;" : "=f"(r) : "f"(x)); return r;
}
__device__ __forceinline__ float fast_lg2(float x)
{
    float r; asm("lg2.approx.ftz.f32 %0, %1;" : "=f"(r) : "f"(x)); return r;
}

// ---------------------------------------------------------------------------
// Kernel 1: emission = log_softmax(embed @ W^T + b)
// emis6 structure (grid 1024, block 128, 32 rows, 16 tiles of 64 cols,
// coalesced smem staging + register prefetch) with 2-row W amortization:
// thread = (rowpair {p, p+16}, 8-col slice s); lane = p + 16*(s&1) so a
// warp covers slices {2w, 2w+1}. W LDS per thread per tile: 24 (was 48).
// ---------------------------------------------------------------------------
__global__ __launch_bounds__(128) void emis9(
    const float* __restrict__ embed,
    const float* __restrict__ W,
    const float* __restrict__ bias,
    const unsigned* __restrict__ tags_words,
    float* __restrict__ out)
{
    __shared__ __align__(16) float sE[32 * 73];   // staging stride 68; red stride 73
    __shared__ __align__(16) float sWt[64 * 12];

    const int tid = threadIdx.x;

    if (blockIdx.x == 0) {
        __shared__ int s_any;
        if (tid == 0) s_any = 0;
        __syncthreads();
        int nz = 0;
        for (int qq = tid; qq < 2048; qq += 128)
            nz |= (tags_words[2 * qq + 1] != 0u);
        if (nz) atomicOr(&s_any, 1);
        __syncthreads();
        if (tid == 0) {
            g_tags64 = s_any ? 0 : 1;
            out[0] = 0.0f;
        }
    }

    const int warp = tid >> 5;
    const int lane = tid & 31;
    const int p = lane & 15;               // rowpair: rows p, p+16
    const int s = warp * 2 + (lane >> 4);  // col slice 0..7 (8 cols each)
    const int rowBase = blockIdx.x * 32;

    // -------- prefetch tile 0 --------
    float4 pe[4];
    float  pw[5];
    {
        const float* gsrc = embed + (size_t)rowBase * EMB;
#pragma unroll
        for (int it = 0; it < 4; ++it) {
            int idx = it * 128 + tid;
            int r2 = idx >> 4, cc = (idx & 15) * 4;
            pe[it] = *(const float4*)(gsrc + (size_t)r2 * EMB + cc);
        }
#pragma unroll
        for (int it = 0; it < 5; ++it) {
            int idx = it * 128 + tid;
            if (idx < 576) {
                int t = idx >> 6, e = idx & 63;
                pw[it] = W[t * EMB + e];
            }
        }
    }

    unsigned long long a01_0 = 0ull, a23_0 = 0ull, a45_0 = 0ull, a67_0 = 0ull;
    unsigned long long a01_1 = 0ull, a23_1 = 0ull, a45_1 = 0ull, a67_1 = 0ull;
    float a8_0 = 0.0f, a8_1 = 0.0f;

    for (int tile = 0; tile < 16; ++tile) {
        __syncthreads();
#pragma unroll
        for (int it = 0; it < 4; ++it) {
            int idx = it * 128 + tid;
            int r2 = idx >> 4, cc = (idx & 15) * 4;
            *(float4*)&sE[r2 * 68 + cc] = pe[it];
        }
#pragma unroll
        for (int it = 0; it < 5; ++it) {
            int idx = it * 128 + tid;
            if (idx < 576) {
                int t = idx >> 6, e = idx & 63;
                sWt[e * 12 + t] = pw[it];
            }
        }
        __syncthreads();

        if (tile < 15) {
            const float* gsrc = embed + (size_t)rowBase * EMB + (tile + 1) * 64;
#pragma unroll
            for (int it = 0; it < 4; ++it) {
                int idx = it * 128 + tid;
                int r2 = idx >> 4, cc = (idx & 15) * 4;
                pe[it] = *(const float4*)(gsrc + (size_t)r2 * EMB + cc);
            }
#pragma unroll
            for (int it = 0; it < 5; ++it) {
                int idx = it * 128 + tid;
                if (idx < 576) {
                    int t = idx >> 6, e = idx & 63;
                    pw[it] = W[t * EMB + (tile + 1) * 64 + e];
                }
            }
        }

        // compute: 8 cols (slice s) x 2 rows (p, p+16)
        const float* xr0 = &sE[p * 68 + s * 8];
        const float* xr1 = &sE[(p + 16) * 68 + s * 8];
        const float* wq  = &sWt[(s * 8) * 12];
#pragma unroll
        for (int e4 = 0; e4 < 8; e4 += 4) {
            float4 xa4 = *(const float4*)(xr0 + e4);
            float4 xb4 = *(const float4*)(xr1 + e4);
#pragma unroll
            for (int u = 0; u < 4; ++u) {
                float xa = (u == 0) ? xa4.x : (u == 1) ? xa4.y : (u == 2) ? xa4.z : xa4.w;
                float xb = (u == 0) ? xb4.x : (u == 1) ? xb4.y : (u == 2) ? xb4.z : xb4.w;
                const float* we = wq + (e4 + u) * 12;
                ulonglong2 wA = *(const ulonglong2*)we;        // {w0,w1},{w2,w3}
                ulonglong2 wB = *(const ulonglong2*)(we + 4);  // {w4,w5},{w6,w7}
                float w8 = we[8];
                unsigned long long da = dup2(xa);
                unsigned long long db = dup2(xb);
                ffma2(a01_0, da, wA.x); ffma2(a23_0, da, wA.y);
                ffma2(a45_0, da, wB.x); ffma2(a67_0, da, wB.y);
                a8_0 = fmaf(xa, w8, a8_0);
                ffma2(a01_1, db, wA.x); ffma2(a23_1, db, wA.y);
                ffma2(a45_1, db, wB.x); ffma2(a67_1, db, wB.y);
                a8_1 = fmaf(xb, w8, a8_1);
            }
        }
    }

    // -------- reduction across slices + log_softmax --------
    __syncthreads();
    float* red = sE;                  // red[row][73]: [s*9 + t]
    {
        float2 f;
        float* r0 = &red[p * 73 + s * 9];
        f = *(float2*)&a01_0; r0[0] = f.x; r0[1] = f.y;
        f = *(float2*)&a23_0; r0[2] = f.x; r0[3] = f.y;
        f = *(float2*)&a45_0; r0[4] = f.x; r0[5] = f.y;
        f = *(float2*)&a67_0; r0[6] = f.x; r0[7] = f.y;
        r0[8] = a8_0;
        float* r1 = &red[(p + 16) * 73 + s * 9];
        f = *(float2*)&a01_1; r1[0] = f.x; r1[1] = f.y;
        f = *(float2*)&a23_1; r1[2] = f.x; r1[3] = f.y;
        f = *(float2*)&a45_1; r1[4] = f.x; r1[5] = f.y;
        f = *(float2*)&a67_1; r1[6] = f.x; r1[7] = f.y;
        r1[8] = a8_1;
    }
    __syncthreads();

    if (tid < 32) {
        const float* rp = &red[tid * 73];
        float acc[NT];
#pragma unroll
        for (int t = 0; t < NT; t++) {
            float sum = bias[t];
#pragma unroll
            for (int qq = 0; qq < 8; qq++) sum += rp[qq * 9 + t];
            acc[t] = sum;
        }

        float mx = acc[0];
#pragma unroll
        for (int t = 1; t < NT; t++) mx = fmaxf(mx, acc[t]);
        float sum = 0.0f;
#pragma unroll
        for (int t = 0; t < NT; t++) sum += fast_ex2((acc[t] - mx) * L2E);
        float lse = fmaf(fast_lg2(sum), LN2, mx);

        float* o = out + 1 + (size_t)(rowBase + tid) * NT;
#pragma unroll
        for (int t = 0; t < NT; t++) o[t] = acc[t] - lse;
    }
}

// ---------------------------------------------------------------------------
// Kernel 2: CRF scan, grid (NQ=8, BATCH) = 512 blocks x 96 threads.
// Block = 64 positions: 8 chunks x 8 steps, thread = (chunk, row i) holding
// v[0..8] in registers. Then 3-level tree combine (8->4->2->1) -> g_M.
// ---------------------------------------------------------------------------
__global__ __launch_bounds__(96) void crf_scan(
    const float* __restrict__ outbuf,       // d_out; emission at +1
    const int*   __restrict__ mask,
    const float* __restrict__ trans)
{
    const float* emis = outbuf + 1;
    const int q = blockIdx.x, b = blockIdx.y;
    const int tid = threadIdx.x;

    __shared__ __align__(16) float sEm[64 * EMP];
    __shared__ int   sMk[64];
    __shared__ float sTr[84];
    __shared__ __align__(16) float sE2[112];         // [k][12] padded
    __shared__ __align__(16) float sMt[CPB][84];
    __shared__ __align__(16) float sEB[4][112];

    const int t0_blk = 1 + q * 64;
    const int n = min(SEQ - t0_blk, 64);             // 64 (q<7) or 63 (q=7)

    const float* em_b = emis + (size_t)b * SEQ * NT + (size_t)t0_blk * NT;
    const int*   mk   = mask + b * SEQ + t0_blk;

    for (int idx = tid; idx < n * NT; idx += 96) {
        int t = idx / NT, j = idx - t * NT;
        sEm[t * EMP + j] = em_b[idx];
    }
    for (int idx = tid; idx < n; idx += 96) sMk[idx] = mk[idx];
    if (tid < 81) {
        float tv = trans[tid];
        sTr[tid] = tv;
        int k = tid / 9, j = tid - k * 9;
        sE2[k * 12 + j] = fast_ex2(tv * L2E);
    }
    __syncthreads();

    // ---- chunk scans: 72 threads = 8 chunks x 9 rows ----
    if (tid < CPB * NT) {
        const int c = tid / NT;
        const int i = tid - c * NT;

        float ti[9];
#pragma unroll
        for (int j = 0; j < 9; j++) ti[j] = sTr[i * 9 + j];

        float v[9];
        bool started = false;

        const int s0 = c * CHUNK_LEN;
        const int s1 = min(n, s0 + CHUNK_LEN);

        for (int s = s0; s < s1; ++s) {
            const int m = sMk[s];
            float4 e0 = *(const float4*)&sEm[s * EMP];
            float4 e4 = *(const float4*)&sEm[s * EMP + 4];
            float  e8 = sEm[s * EMP + 8];
            float emv[9] = {e0.x, e0.y, e0.z, e0.w, e4.x, e4.y, e4.z, e4.w, e8};
            if (m) {
                if (!started) {
#pragma unroll
                    for (int j = 0; j < 9; j++) v[j] = ti[j] + emv[j];
                    started = true;
                } else {
                    const float r = v[0];
                    float e[9];
#pragma unroll
                    for (int k = 0; k < 9; k++) e[k] = fast_ex2((v[k] - r) * L2E);
                    float acc[9];
#pragma unroll
                    for (int j = 0; j < 9; j++) acc[j] = 0.0f;
#pragma unroll
                    for (int k = 0; k < 9; k++) {
                        float4 b0 = *(const float4*)&sE2[k * 12];
                        float4 b4 = *(const float4*)&sE2[k * 12 + 4];
                        float  b8 = sE2[k * 12 + 8];
                        acc[0] = fmaf(e[k], b0.x, acc[0]);
                        acc[1] = fmaf(e[k], b0.y, acc[1]);
                        acc[2] = fmaf(e[k], b0.z, acc[2]);
                        acc[3] = fmaf(e[k], b0.w, acc[3]);
                        acc[4] = fmaf(e[k], b4.x, acc[4]);
                        acc[5] = fmaf(e[k], b4.y, acc[5]);
                        acc[6] = fmaf(e[k], b4.z, acc[6]);
                        acc[7] = fmaf(e[k], b4.w, acc[7]);
                        acc[8] = fmaf(e[k], b8,   acc[8]);
                    }
#pragma unroll
                    for (int j = 0; j < 9; j++)
                        v[j] = fmaf(fast_lg2(acc[j]), LN2, r) + emv[j];
                }
            }
        }
#pragma unroll
        for (int j = 0; j < 9; j++)
            sMt[c][i * 9 + j] = started ? v[j] : ((i == j) ? 0.0f : -1e30f);
    }

    // ---- tree combine: 8 -> 4 -> 2 -> 1 ----
#pragma unroll
    for (int lvl = 0; lvl < 3; ++lvl) {
        const int np = 4 >> lvl;
        const int active = np * NT;
        __syncthreads();
        if (tid < active) {
            const int p = tid / NT, i = tid - (tid / NT) * NT;
            const float* Br = &sMt[2 * p + 1][i * 9];
#pragma unroll
            for (int j = 0; j < 9; j++)
                sEB[p][i * 12 + j] = fast_ex2(Br[j] * L2E);
        }
        __syncthreads();
        float C[9];
        int p = 0, i = 0;
        if (tid < active) {
            p = tid / NT; i = tid - p * NT;
            const float* Ar = &sMt[2 * p][i * 9];
            float a[9];
#pragma unroll
            for (int k = 0; k < 9; k++) a[k] = Ar[k];
            float r = a[0];
#pragma unroll
            for (int k = 1; k < 9; k++) r = fmaxf(r, a[k]);
            float e[9];
#pragma unroll
            for (int k = 0; k < 9; k++) e[k] = fast_ex2((a[k] - r) * L2E);
            float acc[9];
#pragma unroll
            for (int j = 0; j < 9; j++) acc[j] = 0.0f;
#pragma unroll
            for (int k = 0; k < 9; k++) {
                float4 b0 = *(const float4*)&sEB[p][k * 12];
                float4 b4 = *(const float4*)&sEB[p][k * 12 + 4];
                float  b8 = sEB[p][k * 12 + 8];
                acc[0] = fmaf(e[k], b0.x, acc[0]);
                acc[1] = fmaf(e[k], b0.y, acc[1]);
                acc[2] = fmaf(e[k], b0.z, acc[2]);
                acc[3] = fmaf(e[k], b0.w, acc[3]);
                acc[4] = fmaf(e[k], b4.x, acc[4]);
                acc[5] = fmaf(e[k], b4.y, acc[5]);
                acc[6] = fmaf(e[k], b4.z, acc[6]);
                acc[7] = fmaf(e[k], b4.w, acc[7]);
                acc[8] = fmaf(e[k], b8,   acc[8]);
            }
#pragma unroll
            for (int j = 0; j < 9; j++) C[j] = fmaf(fast_lg2(acc[j]), LN2, r);
        }
        __syncthreads();
        if (tid < active) {
#pragma unroll
            for (int j = 0; j < 9; j++) sMt[p][i * 9 + j] = C[j];
        }
    }
    __syncthreads();

    if (tid < 81) g_M[(b * NQ + q) * 81 + tid] = sMt[0][tid];
}

// ---------------------------------------------------------------------------
// Kernel 3: per-batch numerator + 8-matrix combine + denominator + atomicAdd.
// ---------------------------------------------------------------------------
__global__ __launch_bounds__(128) void crf_final2(
    float* __restrict__ outbuf,
    const void* __restrict__ tags,
    const int*  __restrict__ mask,
    const float* __restrict__ startT,
    const float* __restrict__ endT,
    const float* __restrict__ trans)
{
    const float* emis = outbuf + 1;
    const int b = blockIdx.x;
    const int tid = threadIdx.x;
    const int lane = tid & 31;
    const float* em_b = emis + (size_t)b * SEQ * NT;

    __shared__ float sM[NQ * 81];
    __shared__ float sTr[81];
    __shared__ float s_accf;
    __shared__ int   s_msum;
    __shared__ float s_num;

    if (tid == 0) { s_accf = 0.0f; s_msum = 0; }
    if (tid < 81) sTr[tid] = trans[tid];
    for (int idx = tid; idx < NQ * 81; idx += 128)
        sM[idx] = g_M[b * (NQ * 81) + idx];
    __syncthreads();

    // numerator
    {
        const long long* t64 = (const long long*)tags;
        const int*       t32 = (const int*)tags;
        const int is64 = g_tags64;

        float acc = 0.0f;
        int   msum = 0;
#pragma unroll
        for (int rep = 0; rep < 4; rep++) {
            const int s = tid + rep * 128;
            const int m = mask[b * SEQ + s];
            msum += m;
            if (s >= 1) {
                int tp  = is64 ? (int)t64[b * SEQ + s - 1] : t32[b * SEQ + s - 1];
                int tcu = is64 ? (int)t64[b * SEQ + s]     : t32[b * SEQ + s];
                acc += (float)m * (sTr[tp * 9 + tcu] + em_b[s * NT + tcu]);
            }
        }
#pragma unroll
        for (int o = 16; o > 0; o >>= 1) {
            acc  += __shfl_down_sync(0xffffffffu, acc, o);
            msum += __shfl_down_sync(0xffffffffu, msum, o);
        }
        if (lane == 0) {
            atomicAdd(&s_accf, acc);
            atomicAdd(&s_msum, msum);
        }
    }
    __syncthreads();

    if (tid == 0) {
        const long long* t64 = (const long long*)tags;
        const int*       t32 = (const int*)tags;
        const int is64 = g_tags64;
        int tg0  = is64 ? (int)t64[b * SEQ] : t32[b * SEQ];
        int last = s_msum - 1;
        int tl   = is64 ? (int)t64[b * SEQ + last] : t32[b * SEQ + last];
        s_num = s_accf + startT[tg0] + em_b[tg0] + endT[tl];
    }
    __syncthreads();

    // combine + denominator (warp 0, lanes j)
    if (tid < 32) {
        const int j = tid;
        float v = (j < 9) ? (startT[j] + em_b[j]) : -1e30f;
        for (int c = 0; c < NQ; c++) {
            const float* Mc = sM + c * 81;
            float vals[9];
#pragma unroll
            for (int i2 = 0; i2 < 9; i2++) {
                float sv = __shfl_sync(0xffffffffu, v, i2);
                vals[i2] = sv + ((j < 9) ? Mc[i2 * 9 + j] : 0.0f);
            }
            float nv = -1e30f;
            if (j < 9) {
                float mx = vals[0];
#pragma unroll
                for (int i2 = 1; i2 < 9; i2++) mx = fmaxf(mx, vals[i2]);
                float s = 0.0f;
#pragma unroll
                for (int i2 = 0; i2 < 9; i2++) s += fast_ex2((vals[i2] - mx) * L2E);
                nv = fmaf(fast_lg2(s), LN2, mx);
            }
            v = nv;
        }
        float x = (j < 9) ? v + endT[j] : -1e30f;
        float mx = x;
#pragma unroll
        for (int o = 16; o > 0; o >>= 1) mx = fmaxf(mx, __shfl_xor_sync(0xffffffffu, mx, o));
        float e = (j < 9) ? fast_ex2((x - mx) * L2E) : 0.0f;
#pragma unroll
        for (int o = 16; o > 0; o >>= 1) e += __shfl_xor_sync(0xffffffffu, e, o);
        if (tid == 0) {
            float den = fmaf(fast_lg2(e), LN2, mx);
            atomicAdd(outbuf, s_num - den);
        }
    }
}

// ---------------------------------------------------------------------------
extern "C" void kernel_launch(void* const* d_in, const int* in_sizes, int n_in,
                              void* d_out, int out_size)
{
    const float* embed  = (const float*)d_in[0];
    const void*  tags   = d_in[1];
    const int*   mask   = (const int*)d_in[2];
    const float* W      = (const float*)d_in[3];
    const float* bias   = (const float*)d_in[4];
    const float* startT = (const float*)d_in[5];
    const float* endT   = (const float*)d_in[6];
    const float* trans  = (const float*)d_in[7];
    float* out = (float*)d_out;

    emis9<<<(BATCH * SEQ) / 32, 128>>>(embed, W, bias,
                                       (const unsigned*)tags, out);
    dim3 g2(NQ, BATCH);
    crf_scan<<<g2, 96>>>(out, mask, trans);
    crf_final2<<<BATCH, 128>>>(out, tags, mask, startT, endT, trans);
}

// round 11
// speedup vs baseline: 1.0728x; 1.0728x over previous
#include <cuda_runtime.h>
#include <cstdint>

#define NT      9
#define SEQ     512
#define BATCH   64
#define EMB     1024
#define NQ      4               // sequence quarters (scan blocks per batch)
#define CHUNK_LEN 16
#define CPB     8               // chunks per block
#define EMP     12

#define L2E 1.4426950408889634f
#define LN2 0.6931471805599453f

__device__ float g_M[BATCH * NQ * 81];
__device__ float g_num[BATCH];
__device__ int   g_cnt[BATCH];
__device__ int   g_ticket[BATCH];
__device__ int   g_tags64;

__device__ __forceinline__ void ffma2(unsigned long long& acc,
                                      unsigned long long a,
                                      unsigned long long b)
{
    asm("fma.rn.f32x2 %0, %1, %2, %3;" : "=l"(acc) : "l"(a), "l"(b), "l"(acc));
}
__device__ __forceinline__ unsigned long long dup2(float x)
{
    unsigned long long r; asm("mov.b64 %0, {%1,%1};" : "=l"(r) : "f"(x)); return r;
}
__device__ __forceinline__ float fast_ex2(float x)
{
    float r; asm("ex2.approx.ftz.f32 %0, %1;" : "=f"(r) : "f"(x)); return r;
}
__device__ __forceinline__ float fast_lg2(float x)
{
    float r; asm("lg2.approx.ftz.f32 %0, %1;" : "=f"(r) : "f"(x)); return r;
}

// ---------------------------------------------------------------------------
// Kernel 1 (PROVEN emis6, R4): emission = log_softmax(embed @ W^T + b)
// Block 0 additionally zeroes the per-batch CRF accumulators + ll.
// ---------------------------------------------------------------------------
__global__ __launch_bounds__(128) void emis6(
    const float* __restrict__ embed,
    const float* __restrict__ W,
    const float* __restrict__ bias,
    const unsigned* __restrict__ tags_words,
    float* __restrict__ out)
{
    __shared__ float sE[32 * 68];
    __shared__ float sWt[64 * 12];

    const int tid = threadIdx.x;

    if (blockIdx.x == 0) {
        __shared__ int s_any;
        if (tid == 0) s_any = 0;
        __syncthreads();
        int nz = 0;
        for (int qq = tid; qq < 2048; qq += 128)
            nz |= (tags_words[2 * qq + 1] != 0u);
        if (nz) atomicOr(&s_any, 1);
        __syncthreads();
        if (tid == 0) {
            g_tags64 = s_any ? 0 : 1;
            out[0] = 0.0f;
        }
        if (tid < BATCH) {
            g_num[tid] = 0.0f;
            g_cnt[tid] = 0;
            g_ticket[tid] = 0;
        }
    }

    const int q = tid >> 5;
    const int r = tid & 31;
    const int rowBase = blockIdx.x * 32;

    float4 pe[4];
    float  pw[5];
    {
        const float* gsrc = embed + (size_t)rowBase * EMB;
#pragma unroll
        for (int it = 0; it < 4; ++it) {
            int idx = it * 128 + tid;
            int r2 = idx >> 4, cc = (idx & 15) * 4;
            pe[it] = *(const float4*)(gsrc + (size_t)r2 * EMB + cc);
        }
#pragma unroll
        for (int it = 0; it < 5; ++it) {
            int idx = it * 128 + tid;
            if (idx < 576) {
                int t = idx >> 6, e = idx & 63;
                pw[it] = W[t * EMB + e];
            }
        }
    }

    unsigned long long a01 = 0ull, a23 = 0ull, a45 = 0ull, a67 = 0ull;
    float a8 = 0.0f;

    for (int tile = 0; tile < 16; ++tile) {
        __syncthreads();
#pragma unroll
        for (int it = 0; it < 4; ++it) {
            int idx = it * 128 + tid;
            int r2 = idx >> 4, cc = (idx & 15) * 4;
            *(float4*)&sE[r2 * 68 + cc] = pe[it];
        }
#pragma unroll
        for (int it = 0; it < 5; ++it) {
            int idx = it * 128 + tid;
            if (idx < 576) {
                int t = idx >> 6, e = idx & 63;
                sWt[e * 12 + t] = pw[it];
            }
        }
        __syncthreads();

        if (tile < 15) {
            const float* gsrc = embed + (size_t)rowBase * EMB + (tile + 1) * 64;
#pragma unroll
            for (int it = 0; it < 4; ++it) {
                int idx = it * 128 + tid;
                int r2 = idx >> 4, cc = (idx & 15) * 4;
                pe[it] = *(const float4*)(gsrc + (size_t)r2 * EMB + cc);
            }
#pragma unroll
            for (int it = 0; it < 5; ++it) {
                int idx = it * 128 + tid;
                if (idx < 576) {
                    int t = idx >> 6, e = idx & 63;
                    pw[it] = W[t * EMB + (tile + 1) * 64 + e];
                }
            }
        }

        const float* xr = &sE[r * 68 + q * 16];
        const float* wq = &sWt[(q * 16) * 12];
#pragma unroll
        for (int e4 = 0; e4 < 16; e4 += 4) {
            float4 x = *(const float4*)(xr + e4);
#pragma unroll
            for (int u = 0; u < 4; ++u) {
                float xs = (u == 0) ? x.x : (u == 1) ? x.y : (u == 2) ? x.z : x.w;
                const float* we = wq + (e4 + u) * 12;
                ulonglong2 wA = *(const ulonglong2*)we;
                ulonglong2 wB = *(const ulonglong2*)(we + 4);
                float w8 = we[8];
                unsigned long long dx = dup2(xs);
                ffma2(a01, dx, wA.x); ffma2(a23, dx, wA.y);
                ffma2(a45, dx, wB.x); ffma2(a67, dx, wB.y);
                a8 = fmaf(xs, w8, a8);
            }
        }
    }

    __syncthreads();
    float* red = sE;
    {
        float2 f;
        float* rp = &red[r * 37 + q * 9];
        f = *(float2*)&a01; rp[0] = f.x; rp[1] = f.y;
        f = *(float2*)&a23; rp[2] = f.x; rp[3] = f.y;
        f = *(float2*)&a45; rp[4] = f.x; rp[5] = f.y;
        f = *(float2*)&a67; rp[6] = f.x; rp[7] = f.y;
        rp[8] = a8;
    }
    __syncthreads();

    if (tid < 32) {
        const float* rp = &red[tid * 37];
        float acc[NT];
#pragma unroll
        for (int t = 0; t < NT; t++)
            acc[t] = rp[t] + rp[9 + t] + rp[18 + t] + rp[27 + t] + bias[t];

        float mx = acc[0];
#pragma unroll
        for (int t = 1; t < NT; t++) mx = fmaxf(mx, acc[t]);
        float s = 0.0f;
#pragma unroll
        for (int t = 0; t < NT; t++) s += fast_ex2((acc[t] - mx) * L2E);
        float lse = fmaf(fast_lg2(s), LN2, mx);

        float* o = out + 1 + (size_t)(rowBase + tid) * NT;
#pragma unroll
        for (int t = 0; t < NT; t++) o[t] = acc[t] - lse;
    }
}

// ---------------------------------------------------------------------------
// Kernel 2: CRF scan + fused finalize (last-block-done ticket).
// grid (NQ=4, BATCH) = 256 blocks x 96 threads. Block = 128 positions:
// 8 chunks x 16 steps (thread = (chunk, row i), v[0..8] in regs), 3-level
// tree combine -> g_M; quarter's numerator contribution -> g_num/g_cnt;
// last block per batch combines 4 matrices + denominator + ll atomicAdd.
// ---------------------------------------------------------------------------
__global__ __launch_bounds__(96) void crf_scan_fin(
    float* __restrict__ outbuf,             // d_out; emission at +1
    const void* __restrict__ tags,
    const int*  __restrict__ mask,
    const float* __restrict__ startT,
    const float* __restrict__ endT,
    const float* __restrict__ trans)
{
    const float* emis = outbuf + 1;
    const int q = blockIdx.x, b = blockIdx.y;
    const int tid = threadIdx.x;
    const int lane = tid & 31;

    __shared__ __align__(16) float sEm[128 * EMP];
    __shared__ int   sMk[128];
    __shared__ float sTr[84];
    __shared__ __align__(16) float sE2[112];
    __shared__ __align__(16) float sMt[CPB][84];
    __shared__ __align__(16) float sEB[4][112];
    __shared__ float s_accf;
    __shared__ int   s_msum;
    __shared__ int   s_last;

    const int t0_blk = 1 + q * 128;
    const int n = min(SEQ - t0_blk, 128);            // 128 (q<3) or 127 (q=3)

    const float* em_b = emis + (size_t)b * SEQ * NT;
    const float* em_q = em_b + (size_t)t0_blk * NT;
    const int*   mk   = mask + b * SEQ + t0_blk;

    if (tid == 0) { s_accf = 0.0f; s_msum = 0; }
    for (int idx = tid; idx < n * NT; idx += 96) {
        int t = idx / NT, j = idx - t * NT;
        sEm[t * EMP + j] = em_q[idx];
    }
    for (int idx = tid; idx < n; idx += 96) sMk[idx] = mk[idx];
    if (tid < 81) {
        float tv = trans[tid];
        sTr[tid] = tv;
        int k = tid / 9, j = tid - k * 9;
        sE2[k * 12 + j] = fast_ex2(tv * L2E);
    }
    __syncthreads();

    // ---- chunk scans: 72 threads = 8 chunks x 9 rows ----
    if (tid < CPB * NT) {
        const int c = tid / NT;
        const int i = tid - c * NT;

        float ti[9];
#pragma unroll
        for (int j = 0; j < 9; j++) ti[j] = sTr[i * 9 + j];

        float v[9];
        bool started = false;

        const int s0 = c * CHUNK_LEN;
        const int s1 = min(n, s0 + CHUNK_LEN);

        for (int s = s0; s < s1; ++s) {
            const int m = sMk[s];
            float4 e0 = *(const float4*)&sEm[s * EMP];
            float4 e4 = *(const float4*)&sEm[s * EMP + 4];
            float  e8 = sEm[s * EMP + 8];
            float emv[9] = {e0.x, e0.y, e0.z, e0.w, e4.x, e4.y, e4.z, e4.w, e8};
            if (m) {
                if (!started) {
#pragma unroll
                    for (int j = 0; j < 9; j++) v[j] = ti[j] + emv[j];
                    started = true;
                } else {
                    const float r = v[0];
                    float e[9];
#pragma unroll
                    for (int k = 0; k < 9; k++) e[k] = fast_ex2((v[k] - r) * L2E);
                    float acc[9];
#pragma unroll
                    for (int j = 0; j < 9; j++) acc[j] = 0.0f;
#pragma unroll
                    for (int k = 0; k < 9; k++) {
                        float4 b0 = *(const float4*)&sE2[k * 12];
                        float4 b4 = *(const float4*)&sE2[k * 12 + 4];
                        float  b8 = sE2[k * 12 + 8];
                        acc[0] = fmaf(e[k], b0.x, acc[0]);
                        acc[1] = fmaf(e[k], b0.y, acc[1]);
                        acc[2] = fmaf(e[k], b0.z, acc[2]);
                        acc[3] = fmaf(e[k], b0.w, acc[3]);
                        acc[4] = fmaf(e[k], b4.x, acc[4]);
                        acc[5] = fmaf(e[k], b4.y, acc[5]);
                        acc[6] = fmaf(e[k], b4.z, acc[6]);
                        acc[7] = fmaf(e[k], b4.w, acc[7]);
                        acc[8] = fmaf(e[k], b8,   acc[8]);
                    }
#pragma unroll
                    for (int j = 0; j < 9; j++)
                        v[j] = fmaf(fast_lg2(acc[j]), LN2, r) + emv[j];
                }
            }
        }
#pragma unroll
        for (int j = 0; j < 9; j++)
            sMt[c][i * 9 + j] = started ? v[j] : ((i == j) ? 0.0f : -1e30f);
    }

    // ---- numerator contribution for this quarter (all 96 threads) ----
    {
        const long long* t64 = (const long long*)tags;
        const int*       t32 = (const int*)tags;
        const int is64 = g_tags64;

        float acc = 0.0f;
        int   msum = 0;
        for (int idx = tid; idx < n; idx += 96) {
            const int s = t0_blk + idx;         // global position, >= 1
            const int m = sMk[idx];
            msum += m;
            int tp  = is64 ? (int)t64[b * SEQ + s - 1] : t32[b * SEQ + s - 1];
            int tcu = is64 ? (int)t64[b * SEQ + s]     : t32[b * SEQ + s];
            acc += (float)m * (sTr[tp * 9 + tcu] + sEm[idx * EMP + tcu]);
        }
        if (q == 0 && tid == 0) msum += mask[b * SEQ];   // position 0 count
#pragma unroll
        for (int o = 16; o > 0; o >>= 1) {
            acc  += __shfl_down_sync(0xffffffffu, acc, o);
            msum += __shfl_down_sync(0xffffffffu, msum, o);
        }
        if (lane == 0) {
            atomicAdd(&s_accf, acc);
            atomicAdd(&s_msum, msum);
        }
    }

    // ---- tree combine: 8 -> 4 -> 2 -> 1 ----
#pragma unroll
    for (int lvl = 0; lvl < 3; ++lvl) {
        const int np = 4 >> lvl;
        const int active = np * NT;
        __syncthreads();
        if (tid < active) {
            const int p = tid / NT, i = tid - (tid / NT) * NT;
            const float* Br = &sMt[2 * p + 1][i * 9];
#pragma unroll
            for (int j = 0; j < 9; j++)
                sEB[p][i * 12 + j] = fast_ex2(Br[j] * L2E);
        }
        __syncthreads();
        float C[9];
        int p = 0, i = 0;
        if (tid < active) {
            p = tid / NT; i = tid - p * NT;
            const float* Ar = &sMt[2 * p][i * 9];
            float a[9];
#pragma unroll
            for (int k = 0; k < 9; k++) a[k] = Ar[k];
            float r = a[0];
#pragma unroll
            for (int k = 1; k < 9; k++) r = fmaxf(r, a[k]);
            float e[9];
#pragma unroll
            for (int k = 0; k < 9; k++) e[k] = fast_ex2((a[k] - r) * L2E);
            float acc[9];
#pragma unroll
            for (int j = 0; j < 9; j++) acc[j] = 0.0f;
#pragma unroll
            for (int k = 0; k < 9; k++) {
                float4 b0 = *(const float4*)&sEB[p][k * 12];
                float4 b4 = *(const float4*)&sEB[p][k * 12 + 4];
                float  b8 = sEB[p][k * 12 + 8];
                acc[0] = fmaf(e[k], b0.x, acc[0]);
                acc[1] = fmaf(e[k], b0.y, acc[1]);
                acc[2] = fmaf(e[k], b0.z, acc[2]);
                acc[3] = fmaf(e[k], b0.w, acc[3]);
                acc[4] = fmaf(e[k], b4.x, acc[4]);
                acc[5] = fmaf(e[k], b4.y, acc[5]);
                acc[6] = fmaf(e[k], b4.z, acc[6]);
                acc[7] = fmaf(e[k], b4.w, acc[7]);
                acc[8] = fmaf(e[k], b8,   acc[8]);
            }
#pragma unroll
            for (int j = 0; j < 9; j++) C[j] = fmaf(fast_lg2(acc[j]), LN2, r);
        }
        __syncthreads();
        if (tid < active) {
#pragma unroll
            for (int j = 0; j < 9; j++) sMt[p][i * 9 + j] = C[j];
        }
    }
    __syncthreads();

    // ---- publish results + ticket ----
    if (tid < 81) g_M[(b * NQ + q) * 81 + tid] = sMt[0][tid];
    if (tid == 0) {
        atomicAdd(&g_num[b], s_accf);
        atomicAdd(&g_cnt[b], s_msum);
        __threadfence();
        int old = atomicAdd(&g_ticket[b], 1);
        s_last = (old == NQ - 1);
    }
    __syncthreads();

    // ---- finalize (only the last block for this batch) ----
    if (s_last && tid < 32) {
        __threadfence();                    // acquire published data
        const long long* t64 = (const long long*)tags;
        const int*       t32 = (const int*)tags;
        const int is64 = g_tags64;

        const int j = tid;
        float v = (j < 9) ? (startT[j] + em_b[j]) : -1e30f;
        for (int c = 0; c < NQ; c++) {
            const float* Mc = g_M + (b * NQ + c) * 81;
            float vals[9];
#pragma unroll
            for (int i2 = 0; i2 < 9; i2++) {
                float sv = __shfl_sync(0xffffffffu, v, i2);
                vals[i2] = sv + ((j < 9) ? Mc[i2 * 9 + j] : 0.0f);
            }
            float nv = -1e30f;
            if (j < 9) {
                float mx = vals[0];
#pragma unroll
                for (int i2 = 1; i2 < 9; i2++) mx = fmaxf(mx, vals[i2]);
                float s = 0.0f;
#pragma unroll
                for (int i2 = 0; i2 < 9; i2++) s += fast_ex2((vals[i2] - mx) * L2E);
                nv = fmaf(fast_lg2(s), LN2, mx);
            }
            v = nv;
        }
        float x = (j < 9) ? v + endT[j] : -1e30f;
        float mx = x;
#pragma unroll
        for (int o = 16; o > 0; o >>= 1) mx = fmaxf(mx, __shfl_xor_sync(0xffffffffu, mx, o));
        float e = (j < 9) ? fast_ex2((x - mx) * L2E) : 0.0f;
#pragma unroll
        for (int o = 16; o > 0; o >>= 1) e += __shfl_xor_sync(0xffffffffu, e, o);
        if (tid == 0) {
            float den = fmaf(fast_lg2(e), LN2, mx);
            int tg0  = is64 ? (int)t64[b * SEQ] : t32[b * SEQ];
            int last = g_cnt[b] - 1;
            int tl   = is64 ? (int)t64[b * SEQ + last] : t32[b * SEQ + last];
            float num = g_num[b] + startT[tg0] + em_b[tg0] + endT[tl];
            atomicAdd(outbuf, num - den);
        }
    }
}

// ---------------------------------------------------------------------------
extern "C" void kernel_launch(void* const* d_in, const int* in_sizes, int n_in,
                              void* d_out, int out_size)
{
    const float* embed  = (const float*)d_in[0];
    const void*  tags   = d_in[1];
    const int*   mask   = (const int*)d_in[2];
    const float* W      = (const float*)d_in[3];
    const float* bias   = (const float*)d_in[4];
    const float* startT = (const float*)d_in[5];
    const float* endT   = (const float*)d_in[6];
    const float* trans  = (const float*)d_in[7];
    float* out = (float*)d_out;

    emis6<<<(BATCH * SEQ) / 32, 128>>>(embed, W, bias,
                                       (const unsigned*)tags, out);
    dim3 g2(NQ, BATCH);
    crf_scan_fin<<<g2, 96>>>(out, tags, mask, startT, endT, trans);
}